// round 6
// baseline (speedup 1.0000x reference)
#include <cuda_runtime.h>
#include <cstdint>

#define BATCH   16
#define NPTS    4096
#define CIN     64
#define NPOINT  1024
#define NSAMPLE 32
#define R_TOTAL (BATCH*NPOINT*NSAMPLE)   // 524288 rows
#define RPAIRS  (R_TOTAL/2)
#define NCENT   (BATCH*NPOINT)           // 16384

typedef unsigned long long u64;

// ---------------- device scratch (no allocations allowed) ----------------
__device__ float g_new_xyz[BATCH*NPOINT*3];
__device__ int   g_gidx[BATCH*NPOINT*NSAMPLE];
__device__ float g_bufA[(size_t)64*R_TOTAL];    // 134 MB (layer0 out)
__device__ float g_bufB[(size_t)64*R_TOTAL];    // 134 MB (mlp1 out)
__device__ float g_pmax[(size_t)NCENT*128];     // 8 MB pooled raw max
__device__ float g_pmin[(size_t)NCENT*128];     // 8 MB pooled raw min
__device__ float g_sums[256];                   // [0:128)=sum, [128:256)=sumsq
__device__ float g_scale[128];
__device__ float g_shift[128];

// ---------------- f32x2 helpers ----------------
__device__ __forceinline__ u64 pack2(float lo, float hi) {
    u64 r; asm("mov.b64 %0, {%1, %2};" : "=l"(r) : "f"(lo), "f"(hi)); return r;
}
__device__ __forceinline__ void unpack2(u64 v, float& lo, float& hi) {
    asm("mov.b64 {%0, %1}, %2;" : "=f"(lo), "=f"(hi) : "l"(v));
}
__device__ __forceinline__ void fma2(u64& d, u64 a, u64 b) {
    asm("fma.rn.f32x2 %0, %1, %2, %0;" : "+l"(d) : "l"(a), "l"(b));
}
__device__ __forceinline__ u64 add2_(u64 a, u64 b) {
    u64 r; asm("add.rn.f32x2 %0, %1, %2;" : "=l"(r) : "l"(a), "l"(b)); return r;
}
__device__ __forceinline__ u64 mul2_(u64 a, u64 b) {
    u64 r; asm("mul.rn.f32x2 %0, %1, %2;" : "=l"(r) : "l"(a), "l"(b)); return r;
}
__device__ __forceinline__ u64 umax64(u64 a, u64 b) { return a > b ? a : b; }

// ---------------- FPS: one block per batch, 512 thr, 8 pts/thr --------------
// Distances via f32x2 (elementwise rn add/mul, sub as add-of-negation: bit
// identical to reference, no FMA contraction). Per-thread argmax scalar
// (fmax tree + lowest-j priority select). Per-warp reduce = ONE smem
// atomicMax(u64) with key (dist_bits<<32)|~idx (dist>=0 -> order-preserving;
// ~idx -> lowest global index wins ties, matching jnp.argmax). Slots are a
// 4-deep parity ring so resets are 2 barriers away from any same-slot use.
__global__ __launch_bounds__(512) void fps_kernel(const float* __restrict__ xyz,
                                                  float* __restrict__ d_out)
{
    const int b   = blockIdx.x;
    const int tid = threadIdx.x;
    const int lane = tid & 31, wid = tid >> 5;
    const float* xb = xyz + (size_t)b*NPTS*3;

    u64 PX[4], PY[4], PZ[4];
    float dst[8];
#pragma unroll
    for (int q = 0; q < 4; q++) {
        int n0 = tid*8 + 2*q, n1 = n0 + 1;
        PX[q] = pack2(xb[n0*3+0], xb[n1*3+0]);
        PY[q] = pack2(xb[n0*3+1], xb[n1*3+1]);
        PZ[q] = pack2(xb[n0*3+2], xb[n1*3+2]);
    }
#pragma unroll
    for (int j = 0; j < 8; j++) dst[j] = 1e10f;

    __shared__ u64 s_k[4][16];
    if (tid < 64) s_k[tid >> 4][tid & 15] = 0ull;

    float cx = xb[0], cy = xb[1], cz = xb[2];   // first center = point 0

    float* nxo = d_out     + (size_t)b*NPOINT*3;
    float* nxg = g_new_xyz + (size_t)b*NPOINT*3;
    __syncthreads();

    for (int i = 0; i < NPOINT; i++) {
        if (tid == 0) {
            nxo[i*3+0] = cx; nxo[i*3+1] = cy; nxo[i*3+2] = cz;
            nxg[i*3+0] = cx; nxg[i*3+1] = cy; nxg[i*3+2] = cz;
        }
        // reset the slot 2 iterations ahead (ring depth 4 => race-free)
        if (tid < 16) s_k[(i + 2) & 3][tid] = 0ull;

        const u64 vnx = pack2(-cx, -cx);
        const u64 vny = pack2(-cy, -cy);
        const u64 vnz = pack2(-cz, -cz);
        float nd[8];
#pragma unroll
        for (int q = 0; q < 4; q++) {
            u64 dx = add2_(PX[q], vnx);
            u64 dy = add2_(PY[q], vny);
            u64 dz = add2_(PZ[q], vnz);
            u64 d2 = add2_(add2_(mul2_(dx,dx), mul2_(dy,dy)), mul2_(dz,dz));
            float lo, hi; unpack2(d2, lo, hi);
            nd[2*q]   = fminf(dst[2*q],   lo);
            nd[2*q+1] = fminf(dst[2*q+1], hi);
            dst[2*q] = nd[2*q]; dst[2*q+1] = nd[2*q+1];
        }
        // local argmax: max value then lowest j achieving it
        float m01 = fmaxf(nd[0], nd[1]), m23 = fmaxf(nd[2], nd[3]);
        float m45 = fmaxf(nd[4], nd[5]), m67 = fmaxf(nd[6], nd[7]);
        float m = fmaxf(fmaxf(m01, m23), fmaxf(m45, m67));
        int bj = 7;
#pragma unroll
        for (int j = 6; j >= 0; j--) bj = (nd[j] == m) ? j : bj;
        int gidx = tid*8 + bj;
        u64 key;
        asm("mov.b64 %0, {%1, %2};" : "=l"(key)
            : "r"(~gidx), "r"(__float_as_uint(m)));
        atomicMax(&s_k[i & 3][wid], key);
        __syncthreads();

        // redundant final reduce in every warp (single barrier per iteration)
        u64 v = s_k[i & 3][lane & 15];
#pragma unroll
        for (int off = 8; off; off >>= 1)
            v = umax64(v, __shfl_xor_sync(0xffffffffu, v, off));
        int win = ~((int)(unsigned)(v & 0xffffffffull));
        cx = xb[win*3+0]; cy = xb[win*3+1]; cz = xb[win*3+2];
    }
}

// ---------------- ball query: one warp per center ----------------
__global__ __launch_bounds__(128) void ballquery_kernel(const float* __restrict__ xyz)
{
    const int wg   = (blockIdx.x * blockDim.x + threadIdx.x) >> 5;  // center id
    const int lane = threadIdx.x & 31;
    if (wg >= NCENT) return;
    const int b = wg >> 10;
    const float* xb = xyz + (size_t)b*NPTS*3;

    const float cx = g_new_xyz[wg*3+0];
    const float cy = g_new_xyz[wg*3+1];
    const float cz = g_new_xyz[wg*3+2];
    const float sc = __fadd_rn(__fadd_rn(__fmul_rn(cx,cx), __fmul_rn(cy,cy)), __fmul_rn(cz,cz));
    const float TH = (float)(0.9*0.9);   // ref compares sqrt(d2) > radius**2 (!)

    int* gout = g_gidx + (size_t)wg*NSAMPLE;
    int cnt = 0;
    int first_idx = 0;
    bool have_first = false;

    for (int base = 0; base < NPTS; base += 32) {
        const int n = base + lane;
        float x = xb[n*3+0], y = xb[n*3+1], z = xb[n*3+2];
        float sp  = __fadd_rn(__fadd_rn(__fmul_rn(x,x), __fmul_rn(y,y)), __fmul_rn(z,z));
        float dot = __fadd_rn(__fadd_rn(__fmul_rn(cx,x), __fmul_rn(cy,y)), __fmul_rn(cz,z));
        float d2  = __fsub_rn(__fadd_rn(sc, sp), __fmul_rn(2.0f, dot));
        float dist = __fsqrt_rn(fmaxf(d2, 0.0f));
        bool in = !(dist > TH);
        unsigned bits = __ballot_sync(0xffffffffu, in);
        if (!have_first && bits) { first_idx = base + __ffs((int)bits) - 1; have_first = true; }
        if (in) {
            int pos = cnt + __popc(bits & ((1u << lane) - 1u));
            if (pos < NSAMPLE) gout[pos] = n;
        }
        cnt += __popc(bits);
        if (cnt >= NSAMPLE) break;
    }
    if (cnt < NSAMPLE) {
        for (int pos = cnt + lane; pos < NSAMPLE; pos += 32) gout[pos] = first_idx;
    }
}

// ---- shared epilogue: per-channel (sum,sumsq) butterflies + spread atomics ----
__device__ __forceinline__ void stats_epilogue(const u64* acc, int lane, int ocb)
{
    float s2[2], q2[2];
#pragma unroll
    for (int j = 0; j < 64; j++) {
        float lo, hi; unpack2(acc[j], lo, hi);
        float s = lo + hi;
        float q = fmaf(lo, lo, hi*hi);
        u64 sq = pack2(s, q);
#pragma unroll
        for (int off = 16; off; off >>= 1)
            sq = add2_(sq, __shfl_xor_sync(0xffffffffu, sq, off));
        if ((j & 31) == lane) { float a, bq; unpack2(sq, a, bq); s2[j >> 5] = a; q2[j >> 5] = bq; }
    }
#pragma unroll
    for (int mq = 0; mq < 2; mq++) {
        int ch = ocb + lane + 32*mq;
        atomicAdd(&g_sums[ch],       s2[mq]);
        atomicAdd(&g_sums[128 + ch], q2[mq]);
    }
}

// ---------------- layer0: gather + concat + linear (IC=67, OC=64), f32x2 ------
__global__ __launch_bounds__(256) void layer0_kernel(const float* __restrict__ xyz,
                                                     const float* __restrict__ points,
                                                     const float* __restrict__ w,
                                                     const float* __restrict__ bias,
                                                     float* __restrict__ y)
{
    __shared__ u64   sw2[64*64];   // [c][oc], weight duplicated into both halves
    __shared__ float sw3[3*64];    // first 3 input channels (rel xyz), scalar
    __shared__ float sb[64];
    for (int i = threadIdx.x; i < 64*64; i += 256) {
        int c = i >> 6, oc = i & 63;
        float v = w[oc*67 + 3 + c];
        sw2[i] = pack2(v, v);
    }
    if (threadIdx.x < 3*64) {
        int kk = threadIdx.x >> 6, oc = threadIdx.x & 63;
        sw3[threadIdx.x] = w[oc*67 + kk];
    }
    if (threadIdx.x < 64) sb[threadIdx.x] = bias[threadIdx.x];
    __syncthreads();

    const int p  = blockIdx.x*256 + threadIdx.x;   // pair index
    const int r0 = p*2, r1 = r0 + 1;
    const int center = r0 >> 5;
    const int b = center >> 10;
    const int n0 = g_gidx[r0];
    const int n1 = g_gidx[r1];
    const float* pp0 = points + ((size_t)(b*NPTS + n0))*CIN;
    const float* pp1 = points + ((size_t)(b*NPTS + n1))*CIN;
    const float cx = g_new_xyz[center*3+0];
    const float cy = g_new_xyz[center*3+1];
    const float cz = g_new_xyz[center*3+2];
    const float x0a = xyz[(size_t)(b*NPTS+n0)*3+0] - cx;
    const float x1a = xyz[(size_t)(b*NPTS+n0)*3+1] - cy;
    const float x2a = xyz[(size_t)(b*NPTS+n0)*3+2] - cz;
    const float x0b = xyz[(size_t)(b*NPTS+n1)*3+0] - cx;
    const float x1b = xyz[(size_t)(b*NPTS+n1)*3+1] - cy;
    const float x2b = xyz[(size_t)(b*NPTS+n1)*3+2] - cz;

    u64 acc[64];
#pragma unroll
    for (int j = 0; j < 64; j++) {
        float a = sb[j], bvl = sb[j];
        a   = fmaf(sw3[j],       x0a, a);
        a   = fmaf(sw3[64+j],    x1a, a);
        a   = fmaf(sw3[128+j],   x2a, a);
        bvl = fmaf(sw3[j],       x0b, bvl);
        bvl = fmaf(sw3[64+j],    x1b, bvl);
        bvl = fmaf(sw3[128+j],   x2b, bvl);
        acc[j] = pack2(a, bvl);
    }

    float a0 = pp0[0], a1 = pp1[0];
#pragma unroll 1
    for (int c = 0; c < CIN; c++) {
        int cn = (c + 1 < CIN) ? c + 1 : c;
        float na0 = pp0[cn], na1 = pp1[cn];
        u64 xa = pack2(a0, a1);
        const ulonglong2* wrow = (const ulonglong2*)(sw2 + c*64);
#pragma unroll
        for (int q = 0; q < 32; q++) {
            ulonglong2 wv = wrow[q];
            fma2(acc[2*q],   wv.x, xa);
            fma2(acc[2*q+1], wv.y, xa);
        }
        a0 = na0; a1 = na1;
    }
#pragma unroll
    for (int j = 0; j < 64; j++) {
        float lo, hi; unpack2(acc[j], lo, hi);
        ((float2*)(y + (size_t)j*R_TOTAL))[p] = make_float2(lo, hi);
    }
    stats_epilogue(acc, threadIdx.x & 31, 0);
}

// ---------------- mlp1: BN(prev)+relu input, linear 64->64, f32x2 -------------
__global__ __launch_bounds__(256) void mlp_layer_kernel(const float* __restrict__ x,
                                                        const float* __restrict__ w,
                                                        const float* __restrict__ bias,
                                                        float* __restrict__ y)
{
    __shared__ u64   sw2[64*64];
    __shared__ float sb[64];
    __shared__ float ssc[64], ssh[64];
    for (int i = threadIdx.x; i < 64*64; i += 256) {
        int c = i >> 6, oc = i & 63;
        float v = w[oc*64 + c];
        sw2[i] = pack2(v, v);
    }
    if (threadIdx.x < 64) {
        sb[threadIdx.x]  = bias[threadIdx.x];
        ssc[threadIdx.x] = g_scale[threadIdx.x];
        ssh[threadIdx.x] = g_shift[threadIdx.x];
    }
    __syncthreads();

    const int p = blockIdx.x*256 + threadIdx.x;    // pair index
    const float2* x2 = (const float2*)x;

    u64 acc[64];
#pragma unroll
    for (int j = 0; j < 64; j++) acc[j] = pack2(sb[j], sb[j]);

    float2 cur = x2[p];
#pragma unroll 1
    for (int c = 0; c < 64; c++) {
        int cn = (c + 1 < 64) ? c + 1 : c;
        float2 nxt = x2[(size_t)cn*RPAIRS + p];
        float s = ssc[c], h = ssh[c];
        float a0 = fmaxf(fmaf(cur.x, s, h), 0.0f);
        float a1 = fmaxf(fmaf(cur.y, s, h), 0.0f);
        u64 xa = pack2(a0, a1);
        const ulonglong2* wrow = (const ulonglong2*)(sw2 + c*64);
#pragma unroll
        for (int q = 0; q < 32; q++) {
            ulonglong2 wv = wrow[q];
            fma2(acc[2*q],   wv.x, xa);
            fma2(acc[2*q+1], wv.y, xa);
        }
        cur = nxt;
    }
#pragma unroll
    for (int j = 0; j < 64; j++) {
        float lo, hi; unpack2(acc[j], lo, hi);
        ((float2*)(y + (size_t)j*R_TOTAL))[p] = make_float2(lo, hi);
    }
    stats_epilogue(acc, threadIdx.x & 31, 0);
}

// ---------------- mlp2 fused: linear 64->128 (half per blockIdx.y) + in-register
// stats (sum/sumsq -> atomics) + per-center raw max/min pooling (no y write) ----
__global__ __launch_bounds__(256) void mlp2_pool_kernel(const float* __restrict__ x,
                                                        const float* __restrict__ w,
                                                        const float* __restrict__ bias)
{
    __shared__ u64   sw2[64*64];
    __shared__ float sb[64];
    __shared__ float ssc[64], ssh[64];
    const int ocb = blockIdx.y * 64;
    for (int i = threadIdx.x; i < 64*64; i += 256) {
        int c = i >> 6, oc = i & 63;
        float v = w[(ocb + oc)*64 + c];
        sw2[i] = pack2(v, v);
    }
    if (threadIdx.x < 64) {
        sb[threadIdx.x]  = bias[ocb + threadIdx.x];
        ssc[threadIdx.x] = g_scale[threadIdx.x];
        ssh[threadIdx.x] = g_shift[threadIdx.x];
    }
    __syncthreads();

    const int p    = blockIdx.x*256 + threadIdx.x;  // pair index (rows 2p,2p+1)
    const int lane = threadIdx.x & 31;
    const float2* x2 = (const float2*)x;

    u64 acc[64];
#pragma unroll
    for (int j = 0; j < 64; j++) acc[j] = pack2(sb[j], sb[j]);

    float2 cur = x2[p];
#pragma unroll 1
    for (int c = 0; c < 64; c++) {
        int cn = (c + 1 < 64) ? c + 1 : c;
        float2 nxt = x2[(size_t)cn*RPAIRS + p];
        float s = ssc[c], h = ssh[c];
        float a0 = fmaxf(fmaf(cur.x, s, h), 0.0f);
        float a1 = fmaxf(fmaf(cur.y, s, h), 0.0f);
        u64 xa = pack2(a0, a1);
        const ulonglong2* wrow = (const ulonglong2*)(sw2 + c*64);
#pragma unroll
        for (int q = 0; q < 32; q++) {
            ulonglong2 wv = wrow[q];
            fma2(acc[2*q],   wv.x, xa);
            fma2(acc[2*q+1], wv.y, xa);
        }
        cur = nxt;
    }

    // ---- epilogue: 16-lane (one center) max/min butterflies + warp sum/sumsq ----
    float pm[4], pmn[4];       // this lane's retained channels: j = (lane&15)+16k
    float s2[2], q2[2];        // this lane's retained sums:      j = lane + 32m
#pragma unroll
    for (int j = 0; j < 64; j++) {
        float lo, hi; unpack2(acc[j], lo, hi);
        float mx = fmaxf(lo, hi);
        float mn = fminf(lo, hi);
#pragma unroll
        for (int off = 8; off; off >>= 1) {
            mx = fmaxf(mx, __shfl_xor_sync(0xffffffffu, mx, off));
            mn = fminf(mn, __shfl_xor_sync(0xffffffffu, mn, off));
        }
        float s = lo + hi;
        float q = fmaf(lo, lo, hi*hi);
        u64 sq = pack2(s, q);
#pragma unroll
        for (int off = 16; off; off >>= 1)
            sq = add2_(sq, __shfl_xor_sync(0xffffffffu, sq, off));
        if ((j & 15) == (lane & 15)) { pm[j >> 4] = mx; pmn[j >> 4] = mn; }
        if ((j & 31) == lane)        { float a, bq; unpack2(sq, a, bq); s2[j >> 5] = a; q2[j >> 5] = bq; }
    }

    const int cen = p >> 4;   // 16 consecutive pairs = 32 rows = one center
#pragma unroll
    for (int kq = 0; kq < 4; kq++) {
        int ch = ocb + (lane & 15) + kq*16;
        g_pmax[(size_t)cen*128 + ch] = pm[kq];
        g_pmin[(size_t)cen*128 + ch] = pmn[kq];
    }
#pragma unroll
    for (int mq = 0; mq < 2; mq++) {
        int ch = ocb + lane + 32*mq;
        atomicAdd(&g_sums[ch],       s2[mq]);
        atomicAdd(&g_sums[128 + ch], q2[mq]);
    }
}

// ---------------- finalize BN: scale/shift, reset sums ----------------
__global__ void finalize_kernel(const float* __restrict__ gamma,
                                const float* __restrict__ beta, int OC)
{
    const int c = threadIdx.x;   // 128 threads
    const float s  = g_sums[c];
    const float ss = g_sums[128 + c];
    if (c < OC) {
        const float inv = 1.0f / (float)R_TOTAL;
        float mu  = s * inv;
        float var = ss * inv - mu*mu;
        float sc  = gamma[c] / sqrtf(var + 1e-5f);
        g_scale[c] = sc;
        g_shift[c] = fmaf(-mu, sc, beta[c]);
    }
    g_sums[c] = 0.f;
    g_sums[128 + c] = 0.f;
}

// ---------------- final: pick max/min by sign(scale), BN + relu (8 MB) --------
__global__ __launch_bounds__(256) void final_kernel(float* __restrict__ out)
{
    const int idx = blockIdx.x*256 + threadIdx.x;     // NCENT*128
    const int ch = idx & 127;
    const float sc = g_scale[ch], sh = g_shift[ch];
    float v = (sc >= 0.0f) ? g_pmax[idx] : g_pmin[idx];
    out[(size_t)BATCH*NPOINT*3 + idx] = fmaxf(fmaf(v, sc, sh), 0.0f);
}

// ---------------- launcher ----------------
extern "C" void kernel_launch(void* const* d_in, const int* in_sizes, int n_in,
                              void* d_out, int out_size)
{
    (void)in_sizes; (void)n_in; (void)out_size;
    const float* xyz    = (const float*)d_in[0];
    const float* points = (const float*)d_in[1];
    const float* w0  = (const float*)d_in[2];
    const float* b0  = (const float*)d_in[3];
    const float* gm0 = (const float*)d_in[4];
    const float* bt0 = (const float*)d_in[5];
    const float* w1  = (const float*)d_in[6];
    const float* b1  = (const float*)d_in[7];
    const float* gm1 = (const float*)d_in[8];
    const float* bt1 = (const float*)d_in[9];
    const float* w2  = (const float*)d_in[10];
    const float* b2  = (const float*)d_in[11];
    const float* gm2 = (const float*)d_in[12];
    const float* bt2 = (const float*)d_in[13];
    float* out = (float*)d_out;

    float *bufA = nullptr, *bufB = nullptr;
    cudaGetSymbolAddress((void**)&bufA, g_bufA);
    cudaGetSymbolAddress((void**)&bufB, g_bufB);

    fps_kernel<<<BATCH, 512>>>(xyz, out);
    ballquery_kernel<<<NCENT/4, 128>>>(xyz);

    layer0_kernel<<<RPAIRS/256, 256>>>(xyz, points, w0, b0, bufA);
    finalize_kernel<<<1, 128>>>(gm0, bt0, 64);

    mlp_layer_kernel<<<RPAIRS/256, 256>>>(bufA, w1, b1, bufB);
    finalize_kernel<<<1, 128>>>(gm1, bt1, 64);

    mlp2_pool_kernel<<<dim3(RPAIRS/256, 2), 256>>>(bufB, w2, b2);
    finalize_kernel<<<1, 128>>>(gm2, bt2, 128);

    final_kernel<<<(NCENT*128)/256, 256>>>(out);
}

// round 8
// speedup vs baseline: 1.2996x; 1.2996x over previous
#include <cuda_runtime.h>
#include <cstdint>

#define BATCH   16
#define NPTS    4096
#define CIN     64
#define NPOINT  1024
#define NSAMPLE 32
#define R_TOTAL (BATCH*NPOINT*NSAMPLE)   // 524288 rows
#define RPAIRS  (R_TOTAL/2)
#define NCENT   (BATCH*NPOINT)           // 16384

typedef unsigned long long u64;

// ---------------- device scratch (no allocations allowed) ----------------
__device__ float g_new_xyz[BATCH*NPOINT*3];
__device__ int   g_gidx[BATCH*NPOINT*NSAMPLE];
__device__ float g_bufA[(size_t)64*R_TOTAL];    // 134 MB (layer0 out)
__device__ float g_bufB[(size_t)64*R_TOTAL];    // 134 MB (mlp1 out)
__device__ float g_pmax[(size_t)NCENT*128];     // 8 MB pooled raw max
__device__ float g_pmin[(size_t)NCENT*128];     // 8 MB pooled raw min
__device__ float g_sums[256];                   // [0:128)=sum, [128:256)=sumsq
__device__ float g_scale[128];
__device__ float g_shift[128];

// ---------------- f32x2 helpers ----------------
__device__ __forceinline__ u64 pack2(float lo, float hi) {
    u64 r; asm("mov.b64 %0, {%1, %2};" : "=l"(r) : "f"(lo), "f"(hi)); return r;
}
__device__ __forceinline__ void unpack2(u64 v, float& lo, float& hi) {
    asm("mov.b64 {%0, %1}, %2;" : "=f"(lo), "=f"(hi) : "l"(v));
}
__device__ __forceinline__ void fma2(u64& d, u64 a, u64 b) {
    asm("fma.rn.f32x2 %0, %1, %2, %0;" : "+l"(d) : "l"(a), "l"(b));
}
__device__ __forceinline__ u64 add2_(u64 a, u64 b) {
    u64 r; asm("add.rn.f32x2 %0, %1, %2;" : "=l"(r) : "l"(a), "l"(b)); return r;
}
__device__ __forceinline__ u64 mul2_(u64 a, u64 b) {
    u64 r; asm("mul.rn.f32x2 %0, %1, %2;" : "=l"(r) : "l"(a), "l"(b)); return r;
}

// ---------------- FPS: one block per batch, 256 thr, 16 pts/thr --------------
// Distances: f32x2 elementwise rn add/mul (sub = add of negation; bit-identical
// to reference, no FMA contraction). Warp argmax: REDUX.MAX on float bits
// (dist >= 0 -> uint order == float order) + ballot + ffs -> lowest lane =
// lowest global index (thread/warp point ranges are contiguous ascending),
// matching jnp.argmax tie-break. Cross-warp: lane0 plain-stores {bits, idx}
// to a parity double-buffered slot; ONE barrier; every warp redundantly
// REDUX-reduces the 8 slots and fetches the winner's coords from xyz (L1).
__global__ __launch_bounds__(256) void fps_kernel(const float* __restrict__ xyz,
                                                  float* __restrict__ d_out)
{
    const int b   = blockIdx.x;
    const int tid = threadIdx.x;
    const int lane = tid & 31, wid = tid >> 5;   // 8 warps
    const float* xb = xyz + (size_t)b*NPTS*3;

    u64 PX[8], PY[8], PZ[8];
    float dst[16];
#pragma unroll
    for (int q = 0; q < 8; q++) {
        int n0 = tid*16 + 2*q, n1 = n0 + 1;
        PX[q] = pack2(xb[n0*3+0], xb[n1*3+0]);
        PY[q] = pack2(xb[n0*3+1], xb[n1*3+1]);
        PZ[q] = pack2(xb[n0*3+2], xb[n1*3+2]);
    }
#pragma unroll
    for (int j = 0; j < 16; j++) dst[j] = 1e10f;

    __shared__ uint2 s_k[2][8];    // parity double-buffer: {dist_bits, idx}

    float cx = xb[0], cy = xb[1], cz = xb[2];   // first center = point 0

    float* nxo = d_out     + (size_t)b*NPOINT*3;
    float* nxg = g_new_xyz + (size_t)b*NPOINT*3;

    for (int i = 0; i < NPOINT; i++) {
        if (tid == 0) {
            nxo[i*3+0] = cx; nxo[i*3+1] = cy; nxo[i*3+2] = cz;
            nxg[i*3+0] = cx; nxg[i*3+1] = cy; nxg[i*3+2] = cz;
        }
        const u64 vnx = pack2(-cx, -cx);
        const u64 vny = pack2(-cy, -cy);
        const u64 vnz = pack2(-cz, -cz);
#pragma unroll
        for (int q = 0; q < 8; q++) {
            u64 dx = add2_(PX[q], vnx);
            u64 dy = add2_(PY[q], vny);
            u64 dz = add2_(PZ[q], vnz);
            u64 d2 = add2_(add2_(mul2_(dx,dx), mul2_(dy,dy)), mul2_(dz,dz));
            float lo, hi; unpack2(d2, lo, hi);
            dst[2*q]   = fminf(dst[2*q],   lo);
            dst[2*q+1] = fminf(dst[2*q+1], hi);
        }
        // thread-local max (tree) then lowest j achieving it
        float m = dst[0];
#pragma unroll
        for (int j = 1; j < 16; j++) m = fmaxf(m, dst[j]);
        int bj = 15;
#pragma unroll
        for (int j = 14; j >= 0; j--) bj = (dst[j] == m) ? j : bj;
        int gidx = tid*16 + bj;

        // warp argmax via REDUX + ballot (lowest lane wins ties)
        unsigned mb   = __float_as_uint(m);
        unsigned wmax = __reduce_max_sync(0xffffffffu, mb);
        unsigned bal  = __ballot_sync(0xffffffffu, mb == wmax);
        int src  = __ffs(bal) - 1;
        int widx = __shfl_sync(0xffffffffu, gidx, src);
        if (lane == 0) s_k[i & 1][wid] = make_uint2(wmax, (unsigned)widx);
        __syncthreads();

        // redundant cross-warp reduce in every warp (single barrier/iter)
        uint2 kk = s_k[i & 1][lane & 7];
        unsigned v = (lane < 8) ? kk.x : 0u;
        unsigned gmax = __reduce_max_sync(0xffffffffu, v);
        unsigned bal2 = __ballot_sync(0xffffffffu, v == gmax);
        int s2  = __ffs(bal2) - 1;                       // lowest slot = lowest warp
        int win = __shfl_sync(0xffffffffu, (int)kk.y, s2);
        cx = xb[win*3+0]; cy = xb[win*3+1]; cz = xb[win*3+2];
    }
}

// ---------------- ball query: one warp per center ----------------
__global__ __launch_bounds__(128) void ballquery_kernel(const float* __restrict__ xyz)
{
    const int wg   = (blockIdx.x * blockDim.x + threadIdx.x) >> 5;  // center id
    const int lane = threadIdx.x & 31;
    if (wg >= NCENT) return;
    const int b = wg >> 10;
    const float* xb = xyz + (size_t)b*NPTS*3;

    const float cx = g_new_xyz[wg*3+0];
    const float cy = g_new_xyz[wg*3+1];
    const float cz = g_new_xyz[wg*3+2];
    const float sc = __fadd_rn(__fadd_rn(__fmul_rn(cx,cx), __fmul_rn(cy,cy)), __fmul_rn(cz,cz));
    const float TH = (float)(0.9*0.9);   // ref compares sqrt(d2) > radius**2 (!)

    int* gout = g_gidx + (size_t)wg*NSAMPLE;
    int cnt = 0;
    int first_idx = 0;
    bool have_first = false;

    for (int base = 0; base < NPTS; base += 32) {
        const int n = base + lane;
        float x = xb[n*3+0], y = xb[n*3+1], z = xb[n*3+2];
        float sp  = __fadd_rn(__fadd_rn(__fmul_rn(x,x), __fmul_rn(y,y)), __fmul_rn(z,z));
        float dot = __fadd_rn(__fadd_rn(__fmul_rn(cx,x), __fmul_rn(cy,y)), __fmul_rn(cz,z));
        float d2  = __fsub_rn(__fadd_rn(sc, sp), __fmul_rn(2.0f, dot));
        float dist = __fsqrt_rn(fmaxf(d2, 0.0f));
        bool in = !(dist > TH);
        unsigned bits = __ballot_sync(0xffffffffu, in);
        if (!have_first && bits) { first_idx = base + __ffs((int)bits) - 1; have_first = true; }
        if (in) {
            int pos = cnt + __popc(bits & ((1u << lane) - 1u));
            if (pos < NSAMPLE) gout[pos] = n;
        }
        cnt += __popc(bits);
        if (cnt >= NSAMPLE) break;
    }
    if (cnt < NSAMPLE) {
        for (int pos = cnt + lane; pos < NSAMPLE; pos += 32) gout[pos] = first_idx;
    }
}

// ---- shared epilogue: per-channel (sum,sumsq) butterflies + spread atomics ----
__device__ __forceinline__ void stats_epilogue(const u64* acc, int lane, int ocb)
{
    float s2[2], q2[2];
#pragma unroll
    for (int j = 0; j < 64; j++) {
        float lo, hi; unpack2(acc[j], lo, hi);
        float s = lo + hi;
        float q = fmaf(lo, lo, hi*hi);
        u64 sq = pack2(s, q);
#pragma unroll
        for (int off = 16; off; off >>= 1)
            sq = add2_(sq, __shfl_xor_sync(0xffffffffu, sq, off));
        if ((j & 31) == lane) { float a, bq; unpack2(sq, a, bq); s2[j >> 5] = a; q2[j >> 5] = bq; }
    }
#pragma unroll
    for (int mq = 0; mq < 2; mq++) {
        int ch = ocb + lane + 32*mq;
        atomicAdd(&g_sums[ch],       s2[mq]);
        atomicAdd(&g_sums[128 + ch], q2[mq]);
    }
}

// ---------------- layer0: gather + concat + linear (IC=67, OC=64), f32x2 ------
__global__ __launch_bounds__(256) void layer0_kernel(const float* __restrict__ xyz,
                                                     const float* __restrict__ points,
                                                     const float* __restrict__ w,
                                                     const float* __restrict__ bias,
                                                     float* __restrict__ y)
{
    __shared__ u64   sw2[64*64];   // [c][oc], weight duplicated into both halves
    __shared__ float sw3[3*64];    // first 3 input channels (rel xyz), scalar
    __shared__ float sb[64];
    for (int i = threadIdx.x; i < 64*64; i += 256) {
        int c = i >> 6, oc = i & 63;
        float v = w[oc*67 + 3 + c];
        sw2[i] = pack2(v, v);
    }
    if (threadIdx.x < 3*64) {
        int kk = threadIdx.x >> 6, oc = threadIdx.x & 63;
        sw3[threadIdx.x] = w[oc*67 + kk];
    }
    if (threadIdx.x < 64) sb[threadIdx.x] = bias[threadIdx.x];
    __syncthreads();

    const int p  = blockIdx.x*256 + threadIdx.x;   // pair index
    const int r0 = p*2, r1 = r0 + 1;
    const int center = r0 >> 5;
    const int b = center >> 10;
    const int n0 = g_gidx[r0];
    const int n1 = g_gidx[r1];
    const float* pp0 = points + ((size_t)(b*NPTS + n0))*CIN;
    const float* pp1 = points + ((size_t)(b*NPTS + n1))*CIN;
    const float cx = g_new_xyz[center*3+0];
    const float cy = g_new_xyz[center*3+1];
    const float cz = g_new_xyz[center*3+2];
    const float x0a = xyz[(size_t)(b*NPTS+n0)*3+0] - cx;
    const float x1a = xyz[(size_t)(b*NPTS+n0)*3+1] - cy;
    const float x2a = xyz[(size_t)(b*NPTS+n0)*3+2] - cz;
    const float x0b = xyz[(size_t)(b*NPTS+n1)*3+0] - cx;
    const float x1b = xyz[(size_t)(b*NPTS+n1)*3+1] - cy;
    const float x2b = xyz[(size_t)(b*NPTS+n1)*3+2] - cz;

    u64 acc[64];
#pragma unroll
    for (int j = 0; j < 64; j++) {
        float a = sb[j], bvl = sb[j];
        a   = fmaf(sw3[j],       x0a, a);
        a   = fmaf(sw3[64+j],    x1a, a);
        a   = fmaf(sw3[128+j],   x2a, a);
        bvl = fmaf(sw3[j],       x0b, bvl);
        bvl = fmaf(sw3[64+j],    x1b, bvl);
        bvl = fmaf(sw3[128+j],   x2b, bvl);
        acc[j] = pack2(a, bvl);
    }

    float a0 = pp0[0], a1 = pp1[0];
#pragma unroll 1
    for (int c = 0; c < CIN; c++) {
        int cn = (c + 1 < CIN) ? c + 1 : c;
        float na0 = pp0[cn], na1 = pp1[cn];
        u64 xa = pack2(a0, a1);
        const ulonglong2* wrow = (const ulonglong2*)(sw2 + c*64);
#pragma unroll
        for (int q = 0; q < 32; q++) {
            ulonglong2 wv = wrow[q];
            fma2(acc[2*q],   wv.x, xa);
            fma2(acc[2*q+1], wv.y, xa);
        }
        a0 = na0; a1 = na1;
    }
#pragma unroll
    for (int j = 0; j < 64; j++) {
        float lo, hi; unpack2(acc[j], lo, hi);
        ((float2*)(y + (size_t)j*R_TOTAL))[p] = make_float2(lo, hi);
    }
    stats_epilogue(acc, threadIdx.x & 31, 0);
}

// ---------------- mlp1: BN(prev)+relu input, linear 64->64, f32x2 -------------
__global__ __launch_bounds__(256) void mlp_layer_kernel(const float* __restrict__ x,
                                                        const float* __restrict__ w,
                                                        const float* __restrict__ bias,
                                                        float* __restrict__ y)
{
    __shared__ u64   sw2[64*64];
    __shared__ float sb[64];
    __shared__ float ssc[64], ssh[64];
    for (int i = threadIdx.x; i < 64*64; i += 256) {
        int c = i >> 6, oc = i & 63;
        float v = w[oc*64 + c];
        sw2[i] = pack2(v, v);
    }
    if (threadIdx.x < 64) {
        sb[threadIdx.x]  = bias[threadIdx.x];
        ssc[threadIdx.x] = g_scale[threadIdx.x];
        ssh[threadIdx.x] = g_shift[threadIdx.x];
    }
    __syncthreads();

    const int p = blockIdx.x*256 + threadIdx.x;    // pair index
    const float2* x2 = (const float2*)x;

    u64 acc[64];
#pragma unroll
    for (int j = 0; j < 64; j++) acc[j] = pack2(sb[j], sb[j]);

    float2 cur = x2[p];
#pragma unroll 1
    for (int c = 0; c < 64; c++) {
        int cn = (c + 1 < 64) ? c + 1 : c;
        float2 nxt = x2[(size_t)cn*RPAIRS + p];
        float s = ssc[c], h = ssh[c];
        float a0 = fmaxf(fmaf(cur.x, s, h), 0.0f);
        float a1 = fmaxf(fmaf(cur.y, s, h), 0.0f);
        u64 xa = pack2(a0, a1);
        const ulonglong2* wrow = (const ulonglong2*)(sw2 + c*64);
#pragma unroll
        for (int q = 0; q < 32; q++) {
            ulonglong2 wv = wrow[q];
            fma2(acc[2*q],   wv.x, xa);
            fma2(acc[2*q+1], wv.y, xa);
        }
        cur = nxt;
    }
#pragma unroll
    for (int j = 0; j < 64; j++) {
        float lo, hi; unpack2(acc[j], lo, hi);
        ((float2*)(y + (size_t)j*R_TOTAL))[p] = make_float2(lo, hi);
    }
    stats_epilogue(acc, threadIdx.x & 31, 0);
}

// ---------------- mlp2 fused: linear 64->128 (half per blockIdx.y) + in-register
// stats (sum/sumsq -> atomics) + per-center raw max/min pooling (no y write) ----
__global__ __launch_bounds__(256) void mlp2_pool_kernel(const float* __restrict__ x,
                                                        const float* __restrict__ w,
                                                        const float* __restrict__ bias)
{
    __shared__ u64   sw2[64*64];
    __shared__ float sb[64];
    __shared__ float ssc[64], ssh[64];
    const int ocb = blockIdx.y * 64;
    for (int i = threadIdx.x; i < 64*64; i += 256) {
        int c = i >> 6, oc = i & 63;
        float v = w[(ocb + oc)*64 + c];
        sw2[i] = pack2(v, v);
    }
    if (threadIdx.x < 64) {
        sb[threadIdx.x]  = bias[ocb + threadIdx.x];
        ssc[threadIdx.x] = g_scale[threadIdx.x];
        ssh[threadIdx.x] = g_shift[threadIdx.x];
    }
    __syncthreads();

    const int p    = blockIdx.x*256 + threadIdx.x;  // pair index (rows 2p,2p+1)
    const int lane = threadIdx.x & 31;
    const float2* x2 = (const float2*)x;

    u64 acc[64];
#pragma unroll
    for (int j = 0; j < 64; j++) acc[j] = pack2(sb[j], sb[j]);

    float2 cur = x2[p];
#pragma unroll 1
    for (int c = 0; c < 64; c++) {
        int cn = (c + 1 < 64) ? c + 1 : c;
        float2 nxt = x2[(size_t)cn*RPAIRS + p];
        float s = ssc[c], h = ssh[c];
        float a0 = fmaxf(fmaf(cur.x, s, h), 0.0f);
        float a1 = fmaxf(fmaf(cur.y, s, h), 0.0f);
        u64 xa = pack2(a0, a1);
        const ulonglong2* wrow = (const ulonglong2*)(sw2 + c*64);
#pragma unroll
        for (int q = 0; q < 32; q++) {
            ulonglong2 wv = wrow[q];
            fma2(acc[2*q],   wv.x, xa);
            fma2(acc[2*q+1], wv.y, xa);
        }
        cur = nxt;
    }

    // ---- epilogue: 16-lane (one center) max/min butterflies + warp sum/sumsq ----
    float pm[4], pmn[4];       // this lane's retained channels: j = (lane&15)+16k
    float s2[2], q2[2];        // this lane's retained sums:      j = lane + 32m
#pragma unroll
    for (int j = 0; j < 64; j++) {
        float lo, hi; unpack2(acc[j], lo, hi);
        float mx = fmaxf(lo, hi);
        float mn = fminf(lo, hi);
#pragma unroll
        for (int off = 8; off; off >>= 1) {
            mx = fmaxf(mx, __shfl_xor_sync(0xffffffffu, mx, off));
            mn = fminf(mn, __shfl_xor_sync(0xffffffffu, mn, off));
        }
        float s = lo + hi;
        float q = fmaf(lo, lo, hi*hi);
        u64 sq = pack2(s, q);
#pragma unroll
        for (int off = 16; off; off >>= 1)
            sq = add2_(sq, __shfl_xor_sync(0xffffffffu, sq, off));
        if ((j & 15) == (lane & 15)) { pm[j >> 4] = mx; pmn[j >> 4] = mn; }
        if ((j & 31) == lane)        { float a, bq; unpack2(sq, a, bq); s2[j >> 5] = a; q2[j >> 5] = bq; }
    }

    const int cen = p >> 4;   // 16 consecutive pairs = 32 rows = one center
#pragma unroll
    for (int kq = 0; kq < 4; kq++) {
        int ch = ocb + (lane & 15) + kq*16;
        g_pmax[(size_t)cen*128 + ch] = pm[kq];
        g_pmin[(size_t)cen*128 + ch] = pmn[kq];
    }
#pragma unroll
    for (int mq = 0; mq < 2; mq++) {
        int ch = ocb + lane + 32*mq;
        atomicAdd(&g_sums[ch],       s2[mq]);
        atomicAdd(&g_sums[128 + ch], q2[mq]);
    }
}

// ---------------- finalize BN: scale/shift, reset sums ----------------
__global__ void finalize_kernel(const float* __restrict__ gamma,
                                const float* __restrict__ beta, int OC)
{
    const int c = threadIdx.x;   // 128 threads
    const float s  = g_sums[c];
    const float ss = g_sums[128 + c];
    if (c < OC) {
        const float inv = 1.0f / (float)R_TOTAL;
        float mu  = s * inv;
        float var = ss * inv - mu*mu;
        float sc  = gamma[c] / sqrtf(var + 1e-5f);
        g_scale[c] = sc;
        g_shift[c] = fmaf(-mu, sc, beta[c]);
    }
    g_sums[c] = 0.f;
    g_sums[128 + c] = 0.f;
}

// ---------------- final: pick max/min by sign(scale), BN + relu (8 MB) --------
__global__ __launch_bounds__(256) void final_kernel(float* __restrict__ out)
{
    const int idx = blockIdx.x*256 + threadIdx.x;     // NCENT*128
    const int ch = idx & 127;
    const float sc = g_scale[ch], sh = g_shift[ch];
    float v = (sc >= 0.0f) ? g_pmax[idx] : g_pmin[idx];
    out[(size_t)BATCH*NPOINT*3 + idx] = fmaxf(fmaf(v, sc, sh), 0.0f);
}

// ---------------- launcher ----------------
extern "C" void kernel_launch(void* const* d_in, const int* in_sizes, int n_in,
                              void* d_out, int out_size)
{
    (void)in_sizes; (void)n_in; (void)out_size;
    const float* xyz    = (const float*)d_in[0];
    const float* points = (const float*)d_in[1];
    const float* w0  = (const float*)d_in[2];
    const float* b0  = (const float*)d_in[3];
    const float* gm0 = (const float*)d_in[4];
    const float* bt0 = (const float*)d_in[5];
    const float* w1  = (const float*)d_in[6];
    const float* b1  = (const float*)d_in[7];
    const float* gm1 = (const float*)d_in[8];
    const float* bt1 = (const float*)d_in[9];
    const float* w2  = (const float*)d_in[10];
    const float* b2  = (const float*)d_in[11];
    const float* gm2 = (const float*)d_in[12];
    const float* bt2 = (const float*)d_in[13];
    float* out = (float*)d_out;

    float *bufA = nullptr, *bufB = nullptr;
    cudaGetSymbolAddress((void**)&bufA, g_bufA);
    cudaGetSymbolAddress((void**)&bufB, g_bufB);

    fps_kernel<<<BATCH, 256>>>(xyz, out);
    ballquery_kernel<<<NCENT/4, 128>>>(xyz);

    layer0_kernel<<<RPAIRS/256, 256>>>(xyz, points, w0, b0, bufA);
    finalize_kernel<<<1, 128>>>(gm0, bt0, 64);

    mlp_layer_kernel<<<RPAIRS/256, 256>>>(bufA, w1, b1, bufB);
    finalize_kernel<<<1, 128>>>(gm1, bt1, 64);

    mlp2_pool_kernel<<<dim3(RPAIRS/256, 2), 256>>>(bufB, w2, b2);
    finalize_kernel<<<1, 128>>>(gm2, bt2, 128);

    final_kernel<<<(NCENT*128)/256, 256>>>(out);
}